// round 10
// baseline (speedup 1.0000x reference)
#include <cuda_runtime.h>

#define Hh 128
#define Ww 128
#define NB 32
#define CCH 16
#define NITER 30

#define TW 16
#define TH 8
#define IW 18
#define IH 10
#define NPX 128           // pixels per tile (16x8)
#define NTILES 4096
#define NCTA 592          // 148 * 4

typedef unsigned long long ULL;

__device__ float g_bufA[NB*CCH*Hh*Ww];
__device__ float g_bufB[NB*CCH*Hh*Ww];
__device__ unsigned char g_pre[NB*Hh*Ww];
__device__ unsigned char g_alive[NB*Hh*Ww];

__device__ __forceinline__ ULL pk2(float a, float b){
    ULL r; asm("mov.b64 %0, {%1,%2};" : "=l"(r) : "f"(a), "f"(b)); return r;
}
__device__ __forceinline__ void fma2(ULL &d, ULL a, ULL b){
    asm("fma.rn.f32x2 %0, %1, %2, %0;" : "+l"(d) : "l"(a), "l"(b));
}
__device__ __forceinline__ float lo2(ULL v){ return __uint_as_float((unsigned)v); }
__device__ __forceinline__ float hi2(ULL v){ return __uint_as_float((unsigned)(v>>32)); }

__global__ void init_kernel(const float* __restrict__ inp){
    int p = blockIdx.x*blockDim.x + threadIdx.x;
    const int total = NB*CCH*Hh*Ww;
    if (p >= total) return;
    int hw = p % (Hh*Ww);
    int c  = (p / (Hh*Ww)) % CCH;
    int n  = p / (CCH*Hh*Ww);
    float v;
    if (c == 0)       v = 1.0f - inp[(n*10 + 0)*Hh*Ww + hw];
    else if (c <= 10) v = inp[(n*10 + (c-1))*Hh*Ww + hw];
    else              v = 0.0f;
    g_bufA[p] = v;
    if (c == 0) g_alive[n*Hh*Ww + hw] = 1;
}

// smem float layout (total 10048 floats = 40192 B):
//   sw1f: [0, 2304)        w1 transposed [k][o]
//   sw2f: [2304, 3072)     w2 transposed [o][j]
//   spf:  [3072, 7168)     sobel rows [32][128]; after GEMM1: H rows 0..31
//   scf:  [7168, 10048)    cell tile 16*10*18; after GEMM1: H rows 32..47 (first 2048)
__global__ void __launch_bounds__(256, 4)
step_kernel(const float* __restrict__ w1, const float* __restrict__ w2, int parity)
{
    extern __shared__ float smem_f[];
    float* sw1f = smem_f;
    float* sw2f = smem_f + 2304;
    float* spf  = smem_f + 3072;
    float* scf  = smem_f + 7168;

    const float* __restrict__ src = parity ? g_bufB : g_bufA;
    float* __restrict__ dst       = parity ? g_bufA : g_bufB;

    const int tid = threadIdx.x;

    // ---- stage weights ONCE per CTA ----
    for (int i = tid; i < 48*48; i += 256) {
        int k = i / 48, o = i % 48;
        sw1f[i] = w1[o*48 + k];
    }
    for (int i = tid; i < 48*16; i += 256) {
        int o = i >> 4, j = i & 15;
        sw2f[i] = w2[j*48 + o];
    }

    #pragma unroll 1
    for (int tile = blockIdx.x; tile < NTILES; tile += NCTA) {
        const int n   = tile >> 7;          // 128 tiles per image
        const int rem = tile & 127;
        const int gy0 = (rem >> 3) * TH;
        const int gx0 = (rem & 7) * TW;

        // ---- stage cell tile (masked, zero-padded halo) ----
        const unsigned char* arow = g_alive + n*Hh*Ww;
        for (int i = tid; i < CCH*IH*IW; i += 256) {
            int sx = i % IW;
            int t  = i / IW;
            int sy = t % IH;
            int c  = t / IH;
            int gx = gx0 + sx - 1, gy = gy0 + sy - 1;
            float v = 0.0f;
            if ((unsigned)gx < (unsigned)Ww && (unsigned)gy < (unsigned)Hh) {
                int hw = gy*Ww + gx;
                if (arow[hw])
                    v = src[(size_t)(n*CCH + c)*(Hh*Ww) + hw];
            }
            scf[(c*IH + sy)*IW + sx] = v;
        }
        __syncthreads();

        // ---- perception: sobel -> spf rows (cell stays in scf); 64 pairs, 4 thr/pair ----
        {
            const int pair = tid & 63;
            const int q    = tid >> 6;           // 0..3 -> 4 channels each
            const int py = pair >> 3, px2 = pair & 7;
            const int sy = py + 1;
            #pragma unroll
            for (int cc = 0; cc < 4; cc++) {
                int c = 4*q + cc;
                const float2* r0 = (const float2*)(scf + (c*IH + sy - 1)*IW + 2*px2);
                const float2* r1 = (const float2*)((const float*)r0 + IW);
                const float2* r2 = (const float2*)((const float*)r1 + IW);
                float2 v00 = r0[0], v01 = r0[1];
                float2 v10 = r1[0], v11 = r1[1];
                float2 v20 = r2[0], v21 = r2[1];
                float a0=v00.x,a1=v00.y,a2=v01.x,a3=v01.y;
                float m0=v10.x,m1=v10.y,m2=v11.x,m3=v11.y;
                float q0=v20.x,q1=v20.y,q2=v21.x,q3=v21.y;
                float gxl = ((a2 - a0) + 2.f*(m2 - m0) + (q2 - q0)) * 0.125f;
                float gxh = ((a3 - a1) + 2.f*(m3 - m1) + (q3 - q1)) * 0.125f;
                float gyl = ((q0 - a0) + 2.f*(q1 - a1) + (q2 - a2)) * 0.125f;
                float gyh = ((q1 - a1) + 2.f*(q2 - a2) + (q3 - a3)) * 0.125f;
                *(float2*)(spf + c*NPX + 2*pair)        = make_float2(gxl, gxh);
                *(float2*)(spf + (16 + c)*NPX + 2*pair) = make_float2(gyl, gyh);
                if (c == 0) {
                    float t0 = fmaxf(fmaxf(a0,a1),a2);
                    float t1 = fmaxf(fmaxf(m0,m1),m2);
                    float t2 = fmaxf(fmaxf(q0,q1),q2);
                    float pl = fmaxf(fmaxf(t0,t1),t2);
                    float u0 = fmaxf(fmaxf(a1,a2),a3);
                    float u1 = fmaxf(fmaxf(m1,m2),m3);
                    float u2 = fmaxf(fmaxf(q1,q2),q3);
                    float ph = fmaxf(fmaxf(u0,u1),u2);
                    uchar2 pm;
                    pm.x = (pl > 0.1f) ? 1 : 0;
                    pm.y = (ph > 0.1f) ? 1 : 0;
                    *reinterpret_cast<uchar2*>(g_pre + (n*Hh + gy0 + py)*Ww + gx0 + 2*px2) = pm;
                }
            }
        }
        __syncthreads();

        // ---- GEMM1: H = relu(W1*perc); thread = (g in 64 lanes -> px g,g+64; ob of 12 o) ----
        {
            const int g  = tid & 63;
            const int ob = tid >> 6;     // o = 12*ob .. 12*ob+11
            ULL acc[2][6];
            #pragma unroll
            for (int m = 0; m < 2; m++)
                #pragma unroll
                for (int j = 0; j < 6; j++) acc[m][j] = 0ull;

            const int off0 = (((g      ) >> 4) + 1)*IW + ((g      ) & 15) + 1;
            const int off1 = (((g + 64 ) >> 4) + 1)*IW + ((g + 64 ) & 15) + 1;

            // part A: k = 0..15, cell from scf
            #pragma unroll 4
            for (int k = 0; k < 16; k++) {
                float p0 = scf[k*(IH*IW) + off0];
                float p1 = scf[k*(IH*IW) + off1];
                ULL s0 = pk2(p0,p0), s1 = pk2(p1,p1);
                const ulonglong2* wv = (const ulonglong2*)(sw1f + k*48 + 12*ob);
                ulonglong2 wa = wv[0], wb = wv[1], wc = wv[2];
                fma2(acc[0][0], s0, wa.x); fma2(acc[1][0], s1, wa.x);
                fma2(acc[0][1], s0, wa.y); fma2(acc[1][1], s1, wa.y);
                fma2(acc[0][2], s0, wb.x); fma2(acc[1][2], s1, wb.x);
                fma2(acc[0][3], s0, wb.y); fma2(acc[1][3], s1, wb.y);
                fma2(acc[0][4], s0, wc.x); fma2(acc[1][4], s1, wc.x);
                fma2(acc[0][5], s0, wc.y); fma2(acc[1][5], s1, wc.y);
            }
            // part B: k = 16..47, sobel from spf rows 0..31
            #pragma unroll 4
            for (int k2 = 0; k2 < 32; k2++) {
                const float* pr = spf + k2*NPX + g;
                float p0 = pr[0], p1 = pr[64];
                ULL s0 = pk2(p0,p0), s1 = pk2(p1,p1);
                const ulonglong2* wv = (const ulonglong2*)(sw1f + (16 + k2)*48 + 12*ob);
                ulonglong2 wa = wv[0], wb = wv[1], wc = wv[2];
                fma2(acc[0][0], s0, wa.x); fma2(acc[1][0], s1, wa.x);
                fma2(acc[0][1], s0, wa.y); fma2(acc[1][1], s1, wa.y);
                fma2(acc[0][2], s0, wb.x); fma2(acc[1][2], s1, wb.x);
                fma2(acc[0][3], s0, wb.y); fma2(acc[1][3], s1, wb.y);
                fma2(acc[0][4], s0, wc.x); fma2(acc[1][4], s1, wc.x);
                fma2(acc[0][5], s0, wc.y); fma2(acc[1][5], s1, wc.y);
            }
            __syncthreads();   // sp/sc reads done before H overwrites
            // store H: rows 0..31 -> spf, rows 32..47 -> scf
            #pragma unroll
            for (int op = 0; op < 6; op++) {
                int o = 12*ob + 2*op;          // even; pair (o,o+1) never straddles 32
                float* r0 = (o < 32) ? (spf + o*NPX) : (scf + (o - 32)*NPX);
                float* r1 = r0 + NPX;
                r0[g]      = fmaxf(lo2(acc[0][op]), 0.f);
                r0[g + 64] = fmaxf(lo2(acc[1][op]), 0.f);
                r1[g]      = fmaxf(hi2(acc[0][op]), 0.f);
                r1[g + 64] = fmaxf(hi2(acc[1][op]), 0.f);
            }
        }
        __syncthreads();

        // ---- GEMM2: cur = W2*H + residual; thread = (px g2 in 128, jg of 8 j) ----
        {
            const int g2 = tid & 127;
            const int jg = tid >> 7;     // j = 8*jg .. 8*jg+7
            const int py = g2 >> 4, sx = g2 & 15;
            const int hw = (gy0 + py)*Ww + gx0 + sx;

            // residual: masked cell re-read from global
            float r[8];
            {
                const unsigned char a = arow[hw];
                #pragma unroll
                for (int jj = 0; jj < 8; jj++) {
                    int j = 8*jg + jj;
                    r[jj] = a ? src[(size_t)(n*CCH + j)*(Hh*Ww) + hw] : 0.0f;
                }
            }

            ULL c0[4];
            #pragma unroll
            for (int q = 0; q < 4; q++) c0[q] = 0ull;

            #pragma unroll 8
            for (int o = 0; o < 32; o++) {
                float h = spf[o*NPX + g2];
                ULL s = pk2(h,h);
                const ulonglong2* wv = (const ulonglong2*)(sw2f + o*16 + 8*jg);
                ulonglong2 w0 = wv[0], w1v = wv[1];
                fma2(c0[0], s, w0.x); fma2(c0[1], s, w0.y);
                fma2(c0[2], s, w1v.x); fma2(c0[3], s, w1v.y);
            }
            #pragma unroll 8
            for (int o = 32; o < 48; o++) {
                float h = scf[(o - 32)*NPX + g2];
                ULL s = pk2(h,h);
                const ulonglong2* wv = (const ulonglong2*)(sw2f + o*16 + 8*jg);
                ulonglong2 w0 = wv[0], w1v = wv[1];
                fma2(c0[0], s, w0.x); fma2(c0[1], s, w0.y);
                fma2(c0[2], s, w1v.x); fma2(c0[3], s, w1v.y);
            }

            #pragma unroll
            for (int q = 0; q < 4; q++) {
                int j = 8*jg + 2*q;
                float* d0 = dst + (size_t)(n*CCH + j)*(Hh*Ww);
                float* d1 = d0 + Hh*Ww;
                d0[hw] = lo2(c0[q]) + r[2*q];
                d1[hw] = hi2(c0[q]) + r[2*q + 1];
            }
        }
        __syncthreads();   // H reads done before next tile's staging writes scf/spf
    }
}

// post mask (3x3 maxpool of new cur ch0) & alive byte; last iter writes output.
__global__ void alive_kernel(float* __restrict__ outfinal, int parity, int writeOut)
{
    const float* __restrict__ cur = parity ? g_bufA : g_bufB;
    int p = blockIdx.x*blockDim.x + threadIdx.x;
    if (p >= NB*Hh*Ww) return;
    int x = p % Ww;
    int y = (p / Ww) % Hh;
    int n = p / (Hh*Ww);
    const float* c0 = cur + (size_t)n*CCH*Hh*Ww;
    float m = -1e30f;
    #pragma unroll
    for (int dy = -1; dy <= 1; dy++) {
        int yy = y + dy;
        if (yy < 0 || yy >= Hh) continue;
        const float* row = c0 + yy*Ww;
        #pragma unroll
        for (int dx = -1; dx <= 1; dx++) {
            int xx = x + dx;
            if (xx < 0 || xx >= Ww) continue;
            m = fmaxf(m, row[xx]);
        }
    }
    bool alive = (m > 0.1f) && (g_pre[p] != 0);
    g_alive[p] = alive ? 1 : 0;
    if (writeOut) {
        size_t base = ((size_t)n*CCH)*Hh*Ww + (size_t)y*Ww + x;
        #pragma unroll
        for (int c = 1; c <= 10; c++) {
            float v = alive ? cur[base + (size_t)c*Hh*Ww] : 0.0f;
            outfinal[(((size_t)n*10 + (c-1))*Hh + y)*Ww + x] = v;
        }
    }
}

extern "C" void kernel_launch(void* const* d_in, const int* in_sizes, int n_in,
                              void* d_out, int out_size)
{
    const float *inp = nullptr, *w1 = nullptr, *w2 = nullptr;
    for (int i = 0; i < n_in; i++) {
        if (in_sizes[i] == 48*48)      w1 = (const float*)d_in[i];
        else if (in_sizes[i] == 16*48) w2 = (const float*)d_in[i];
        else                           inp = (const float*)d_in[i];
    }
    float* out = (float*)d_out;

    const int smemBytes = 10048*4;   // 40192 B
    cudaFuncSetAttribute(step_kernel, cudaFuncAttributeMaxDynamicSharedMemorySize, smemBytes);

    init_kernel<<<(NB*CCH*Hh*Ww + 255)/256, 256>>>(inp);

    const int g2 = (NB*Hh*Ww + 255)/256;
    for (int it = 0; it < NITER; it++) {
        int parity = it & 1;
        step_kernel<<<NCTA, 256, smemBytes>>>(w1, w2, parity);
        alive_kernel<<<g2, 256>>>(out, parity, (it == NITER-1) ? 1 : 0);
    }
}

// round 12
// speedup vs baseline: 1.0206x; 1.0206x over previous
#include <cuda_runtime.h>

#define Hh 128
#define Ww 128
#define NB 32
#define CCH 16
#define NITER 30

#define TW 16
#define TH 16
#define IW 18
#define IH 18
#define NPX 256           // pixels per tile
#define NTILES 2048
#define NCTA 444          // 148 * 3

typedef unsigned long long ULL;

__device__ float g_bufA[NB*CCH*Hh*Ww];
__device__ float g_bufB[NB*CCH*Hh*Ww];
__device__ unsigned char g_pre[NB*Hh*Ww];

__device__ __forceinline__ ULL pk2(float a, float b){
    ULL r; asm("mov.b64 %0, {%1,%2};" : "=l"(r) : "f"(a), "f"(b)); return r;
}
__device__ __forceinline__ void fma2(ULL &d, ULL a, ULL b){
    asm("fma.rn.f32x2 %0, %1, %2, %0;" : "+l"(d) : "l"(a), "l"(b));
}
__device__ __forceinline__ float lo2(ULL v){ return __uint_as_float((unsigned)v); }
__device__ __forceinline__ float hi2(ULL v){ return __uint_as_float((unsigned)(v>>32)); }

__global__ void init_kernel(const float* __restrict__ inp){
    int p = blockIdx.x*blockDim.x + threadIdx.x;
    const int total = NB*CCH*Hh*Ww;
    if (p >= total) return;
    int hw = p % (Hh*Ww);
    int c  = (p / (Hh*Ww)) % CCH;
    int n  = p / (CCH*Hh*Ww);
    float v;
    if (c == 0)       v = 1.0f - inp[(n*10 + 0)*Hh*Ww + hw];
    else if (c <= 10) v = inp[(n*10 + (c-1))*Hh*Ww + hw];
    else              v = 0.0f;
    g_bufA[p] = v;
}

// smem float layout:
//   sw1f:   [0, 2304)        w1 transposed [k][o]
//   sw2f:   [2304, 3072)     w2 transposed [o][j]
//   spf:    [3072, 11264)    sobel rows [32][256]; after GEMM1: H rows 0..31
//   scf:    [11264, 16448)   masked cell tile 16*18*18; after GEMM1: H rows 32..47
//   sc0:    [16448, 16848)   cur ch0 with 2-halo (20*20)
//   salive: bytes at [16848]  18*18 alive mask
__global__ void __launch_bounds__(256, 3)
step_kernel(const float* __restrict__ w1, const float* __restrict__ w2,
            int parity, int first)
{
    extern __shared__ float smem_f[];
    float* sw1f = smem_f;
    float* sw2f = smem_f + 2304;
    float* spf  = smem_f + 3072;
    float* scf  = smem_f + 11264;
    float* sc0  = smem_f + 16448;
    unsigned char* salive = (unsigned char*)(smem_f + 16848);

    const float* __restrict__ src = parity ? g_bufB : g_bufA;
    float* __restrict__ dst       = parity ? g_bufA : g_bufB;

    const int tid = threadIdx.x;

    // ---- stage weights ONCE per CTA (plain floats, transposed) ----
    for (int i = tid; i < 48*48; i += 256) {
        int k = i / 48, o = i % 48;
        sw1f[i] = w1[o*48 + k];
    }
    for (int i = tid; i < 48*16; i += 256) {
        int o = i >> 4, j = i & 15;
        sw2f[i] = w2[j*48 + o];
    }

    #pragma unroll 1
    for (int tile = blockIdx.x; tile < NTILES; tile += NCTA) {
        const int n   = tile >> 6;
        const int rem = tile & 63;
        const int gy0 = (rem >> 3) * TH;
        const int gx0 = (rem & 7) * TW;

        // ---- stage cur ch0 with 2-halo (zero pad; 0-pad ≡ -inf for >0.1 test) ----
        for (int i = tid; i < 20*20; i += 256) {
            int sx = i % 20, sy = i / 20;
            int gx = gx0 + sx - 2, gy = gy0 + sy - 2;
            float v = 0.0f;
            if ((unsigned)gx < (unsigned)Ww && (unsigned)gy < (unsigned)Hh)
                v = src[(size_t)(n*CCH)*(Hh*Ww) + gy*Ww + gx];
            sc0[i] = v;
        }
        __syncthreads();

        // ---- alive = pre & post for the 18x18 (1-halo) region ----
        for (int i = tid; i < 18*18; i += 256) {
            int sx = i % 18, sy = i / 18;
            const float* r0 = sc0 + sy*20 + sx;
            float m = fmaxf(fmaxf(r0[0],  r0[1]),  r0[2]);
            m = fmaxf(m, fmaxf(fmaxf(r0[20], r0[21]), r0[22]));
            m = fmaxf(m, fmaxf(fmaxf(r0[40], r0[41]), r0[42]));
            unsigned char a = 0;
            if (first) a = 1;
            else {
                int gx = gx0 + sx - 1, gy = gy0 + sy - 1;
                if ((unsigned)gx < (unsigned)Ww && (unsigned)gy < (unsigned)Hh)
                    a = (g_pre[(n*Hh + gy)*Ww + gx] && m > 0.1f) ? 1 : 0;
            }
            salive[i] = a;
        }
        __syncthreads();

        // ---- stage masked cell tile ----
        for (int i = tid; i < CCH*IH*IW; i += 256) {
            int sx = i % IW;
            int t  = i / IW;
            int sy = t % IH;
            int c  = t / IH;
            int gx = gx0 + sx - 1, gy = gy0 + sy - 1;
            float v = 0.0f;
            if ((unsigned)gx < (unsigned)Ww && (unsigned)gy < (unsigned)Hh && salive[sy*IW + sx])
                v = src[(size_t)(n*CCH + c)*(Hh*Ww) + gy*Ww + gx];
            scf[(c*IH + sy)*IW + sx] = v;
        }
        __syncthreads();

        // ---- perception: sobel -> spf rows (cell stays in scf) ----
        {
            const int pair = tid & 127;          // 128 pixel-pairs
            const int q    = tid >> 7;           // 0..1 -> 8 channels each
            const int py = pair >> 3, px2 = pair & 7;
            const int sy = py + 1;
            #pragma unroll
            for (int cc = 0; cc < 8; cc++) {
                int c = 8*q + cc;
                const float2* r0 = (const float2*)(scf + (c*IH + sy - 1)*IW + 2*px2);
                const float2* r1 = (const float2*)((const float*)r0 + IW);
                const float2* r2 = (const float2*)((const float*)r1 + IW);
                float2 v00 = r0[0], v01 = r0[1];
                float2 v10 = r1[0], v11 = r1[1];
                float2 v20 = r2[0], v21 = r2[1];
                float a0=v00.x,a1=v00.y,a2=v01.x,a3=v01.y;
                float m0=v10.x,m1=v10.y,m2=v11.x,m3=v11.y;
                float q0=v20.x,q1=v20.y,q2=v21.x,q3=v21.y;
                float gxl = ((a2 - a0) + 2.f*(m2 - m0) + (q2 - q0)) * 0.125f;
                float gxh = ((a3 - a1) + 2.f*(m3 - m1) + (q3 - q1)) * 0.125f;
                float gyl = ((q0 - a0) + 2.f*(q1 - a1) + (q2 - a2)) * 0.125f;
                float gyh = ((q1 - a1) + 2.f*(q2 - a2) + (q3 - a3)) * 0.125f;
                *(float2*)(spf + c*NPX + 2*pair)        = make_float2(gxl, gxh);
                *(float2*)(spf + (16 + c)*NPX + 2*pair) = make_float2(gyl, gyh);
                if (c == 0) {
                    float t0 = fmaxf(fmaxf(a0,a1),a2);
                    float t1 = fmaxf(fmaxf(m0,m1),m2);
                    float t2 = fmaxf(fmaxf(q0,q1),q2);
                    float pl = fmaxf(fmaxf(t0,t1),t2);
                    float u0 = fmaxf(fmaxf(a1,a2),a3);
                    float u1 = fmaxf(fmaxf(m1,m2),m3);
                    float u2 = fmaxf(fmaxf(q1,q2),q3);
                    float ph = fmaxf(fmaxf(u0,u1),u2);
                    uchar2 pm;
                    pm.x = (pl > 0.1f) ? 1 : 0;
                    pm.y = (ph > 0.1f) ? 1 : 0;
                    *reinterpret_cast<uchar2*>(g_pre + (n*Hh + gy0 + py)*Ww + gx0 + 2*px2) = pm;
                }
            }
        }
        __syncthreads();

        // ---- GEMM1: H = relu(W1*perc); thread = (g in 64 px-lanes, ob of 12 o) ----
        {
            const int g  = tid & 63;     // px = g + 64m, m=0..3
            const int ob = tid >> 6;     // o = 12*ob .. 12*ob+11
            ULL acc[4][6];
            #pragma unroll
            for (int m = 0; m < 4; m++)
                #pragma unroll
                for (int j = 0; j < 6; j++) acc[m][j] = 0ull;

            int offm[4];
            #pragma unroll
            for (int m = 0; m < 4; m++) {
                int px = g + 64*m;
                offm[m] = ((px >> 4) + 1)*IW + (px & 15) + 1;
            }

            // part A: k = 0..15, cell from scf
            #pragma unroll 4
            for (int k = 0; k < 16; k++) {
                float p0 = scf[k*(IH*IW) + offm[0]];
                float p1 = scf[k*(IH*IW) + offm[1]];
                float p2 = scf[k*(IH*IW) + offm[2]];
                float p3 = scf[k*(IH*IW) + offm[3]];
                ULL s0 = pk2(p0,p0), s1 = pk2(p1,p1), s2 = pk2(p2,p2), s3 = pk2(p3,p3);
                const ulonglong2* wv = (const ulonglong2*)(sw1f + k*48 + 12*ob);
                ulonglong2 w0 = wv[0], w1v = wv[1], w2v = wv[2];
                fma2(acc[0][0], s0, w0.x);  fma2(acc[1][0], s1, w0.x);  fma2(acc[2][0], s2, w0.x);  fma2(acc[3][0], s3, w0.x);
                fma2(acc[0][1], s0, w0.y);  fma2(acc[1][1], s1, w0.y);  fma2(acc[2][1], s2, w0.y);  fma2(acc[3][1], s3, w0.y);
                fma2(acc[0][2], s0, w1v.x); fma2(acc[1][2], s1, w1v.x); fma2(acc[2][2], s2, w1v.x); fma2(acc[3][2], s3, w1v.x);
                fma2(acc[0][3], s0, w1v.y); fma2(acc[1][3], s1, w1v.y); fma2(acc[2][3], s2, w1v.y); fma2(acc[3][3], s3, w1v.y);
                fma2(acc[0][4], s0, w2v.x); fma2(acc[1][4], s1, w2v.x); fma2(acc[2][4], s2, w2v.x); fma2(acc[3][4], s3, w2v.x);
                fma2(acc[0][5], s0, w2v.y); fma2(acc[1][5], s1, w2v.y); fma2(acc[2][5], s2, w2v.y); fma2(acc[3][5], s3, w2v.y);
            }
            // part B: k = 16..47, sobel from spf rows 0..31
            #pragma unroll 4
            for (int k2 = 0; k2 < 32; k2++) {
                const float* pr = spf + k2*NPX + g;
                float p0 = pr[0], p1 = pr[64], p2 = pr[128], p3 = pr[192];
                ULL s0 = pk2(p0,p0), s1 = pk2(p1,p1), s2 = pk2(p2,p2), s3 = pk2(p3,p3);
                const ulonglong2* wv = (const ulonglong2*)(sw1f + (16 + k2)*48 + 12*ob);
                ulonglong2 w0 = wv[0], w1v = wv[1], w2v = wv[2];
                fma2(acc[0][0], s0, w0.x);  fma2(acc[1][0], s1, w0.x);  fma2(acc[2][0], s2, w0.x);  fma2(acc[3][0], s3, w0.x);
                fma2(acc[0][1], s0, w0.y);  fma2(acc[1][1], s1, w0.y);  fma2(acc[2][1], s2, w0.y);  fma2(acc[3][1], s3, w0.y);
                fma2(acc[0][2], s0, w1v.x); fma2(acc[1][2], s1, w1v.x); fma2(acc[2][2], s2, w1v.x); fma2(acc[3][2], s3, w1v.x);
                fma2(acc[0][3], s0, w1v.y); fma2(acc[1][3], s1, w1v.y); fma2(acc[2][3], s2, w1v.y); fma2(acc[3][3], s3, w1v.y);
                fma2(acc[0][4], s0, w2v.x); fma2(acc[1][4], s1, w2v.x); fma2(acc[2][4], s2, w2v.x); fma2(acc[3][4], s3, w2v.x);
                fma2(acc[0][5], s0, w2v.y); fma2(acc[1][5], s1, w2v.y); fma2(acc[2][5], s2, w2v.y); fma2(acc[3][5], s3, w2v.y);
            }
            __syncthreads();   // sp/sc reads done before H overwrites
            // store H: rows 0..31 -> spf, rows 32..47 -> scf
            #pragma unroll
            for (int op = 0; op < 6; op++) {
                int o = 12*ob + 2*op;          // o even; pair (o, o+1) never straddles 32
                float* r0 = (o < 32) ? (spf + o*NPX) : (scf + (o - 32)*NPX);
                float* r1 = r0 + NPX;
                #pragma unroll
                for (int m = 0; m < 4; m++) {
                    r0[g + 64*m] = fmaxf(lo2(acc[m][op]), 0.f);
                    r1[g + 64*m] = fmaxf(hi2(acc[m][op]), 0.f);
                }
            }
        }
        __syncthreads();

        // ---- GEMM2: cur = W2*H + residual; thread = (g2 in 128, jg of 8 j) ----
        {
            const int g2 = tid & 127;    // px = g2, g2+128
            const int jg = tid >> 7;     // j = 8*jg .. 8*jg+7
            const int pxA = g2, pxB = g2 + 128;
            const int pyA = pxA >> 4, sxA = pxA & 15;
            const int pyB = pxB >> 4, sxB = pxB & 15;
            const int hwA = (gy0 + pyA)*Ww + gx0 + sxA;
            const int hwB = (gy0 + pyB)*Ww + gx0 + sxB;

            // residual: masked cell re-read from global (mask from smem alive)
            float rA[8], rB[8];
            {
                const unsigned char aA = salive[(pyA + 1)*IW + sxA + 1];
                const unsigned char aB = salive[(pyB + 1)*IW + sxB + 1];
                #pragma unroll
                for (int jj = 0; jj < 8; jj++) {
                    int j = 8*jg + jj;
                    const float* sj = src + (size_t)(n*CCH + j)*(Hh*Ww);
                    rA[jj] = aA ? sj[hwA] : 0.0f;
                    rB[jj] = aB ? sj[hwB] : 0.0f;
                }
            }

            ULL c0[4], c1[4];
            #pragma unroll
            for (int q = 0; q < 4; q++) { c0[q] = 0ull; c1[q] = 0ull; }

            #pragma unroll 8
            for (int o = 0; o < 32; o++) {
                const float* hs = spf + o*NPX;
                float ha = hs[g2], hb = hs[g2 + 128];
                ULL sa = pk2(ha,ha), sb = pk2(hb,hb);
                const ulonglong2* wv = (const ulonglong2*)(sw2f + o*16 + 8*jg);
                ulonglong2 w0 = wv[0], w1v = wv[1];
                fma2(c0[0], sa, w0.x); fma2(c0[1], sa, w0.y);
                fma2(c0[2], sa, w1v.x); fma2(c0[3], sa, w1v.y);
                fma2(c1[0], sb, w0.x); fma2(c1[1], sb, w0.y);
                fma2(c1[2], sb, w1v.x); fma2(c1[3], sb, w1v.y);
            }
            #pragma unroll 8
            for (int o = 32; o < 48; o++) {
                const float* hs = scf + (o - 32)*NPX;
                float ha = hs[g2], hb = hs[g2 + 128];
                ULL sa = pk2(ha,ha), sb = pk2(hb,hb);
                const ulonglong2* wv = (const ulonglong2*)(sw2f + o*16 + 8*jg);
                ulonglong2 w0 = wv[0], w1v = wv[1];
                fma2(c0[0], sa, w0.x); fma2(c0[1], sa, w0.y);
                fma2(c0[2], sa, w1v.x); fma2(c0[3], sa, w1v.y);
                fma2(c1[0], sb, w0.x); fma2(c1[1], sb, w0.y);
                fma2(c1[2], sb, w1v.x); fma2(c1[3], sb, w1v.y);
            }

            // store with residual
            #pragma unroll
            for (int q = 0; q < 4; q++) {
                int j = 8*jg + 2*q;
                float* d0 = dst + (size_t)(n*CCH + j)*(Hh*Ww);
                float* d1 = d0 + Hh*Ww;
                d0[hwA] = lo2(c0[q]) + rA[2*q];
                d1[hwA] = hi2(c0[q]) + rA[2*q + 1];
                d0[hwB] = lo2(c1[q]) + rB[2*q];
                d1[hwB] = hi2(c1[q]) + rB[2*q + 1];
            }
        }
        __syncthreads();   // H/alive reads done before next tile's staging
    }
}

// Final: post mask (3x3 maxpool of final cur ch0) & pre; write 10 output channels.
__global__ void final_kernel(float* __restrict__ outfinal, int parity)
{
    const float* __restrict__ cur = parity ? g_bufA : g_bufB;
    int p = blockIdx.x*blockDim.x + threadIdx.x;
    if (p >= NB*Hh*Ww) return;
    int x = p % Ww;
    int y = (p / Ww) % Hh;
    int n = p / (Hh*Ww);
    const float* c0 = cur + (size_t)n*CCH*Hh*Ww;
    float m = -1e30f;
    #pragma unroll
    for (int dy = -1; dy <= 1; dy++) {
        int yy = y + dy;
        if (yy < 0 || yy >= Hh) continue;
        const float* row = c0 + yy*Ww;
        #pragma unroll
        for (int dx = -1; dx <= 1; dx++) {
            int xx = x + dx;
            if (xx < 0 || xx >= Ww) continue;
            m = fmaxf(m, row[xx]);
        }
    }
    bool alive = (m > 0.1f) && (g_pre[p] != 0);
    size_t base = ((size_t)n*CCH)*Hh*Ww + (size_t)y*Ww + x;
    #pragma unroll
    for (int c = 1; c <= 10; c++) {
        float v = alive ? cur[base + (size_t)c*Hh*Ww] : 0.0f;
        outfinal[(((size_t)n*10 + (c-1))*Hh + y)*Ww + x] = v;
    }
}

extern "C" void kernel_launch(void* const* d_in, const int* in_sizes, int n_in,
                              void* d_out, int out_size)
{
    const float *inp = nullptr, *w1 = nullptr, *w2 = nullptr;
    for (int i = 0; i < n_in; i++) {
        if (in_sizes[i] == 48*48)      w1 = (const float*)d_in[i];
        else if (in_sizes[i] == 16*48) w2 = (const float*)d_in[i];
        else                           inp = (const float*)d_in[i];
    }
    float* out = (float*)d_out;

    // 16448 + 400 + 84 = 16932 floats = 67728 B
    const int smemBytes = 16932*4;
    cudaFuncSetAttribute(step_kernel, cudaFuncAttributeMaxDynamicSharedMemorySize, smemBytes);

    init_kernel<<<(NB*CCH*Hh*Ww + 255)/256, 256>>>(inp);

    for (int it = 0; it < NITER; it++) {
        step_kernel<<<NCTA, 256, smemBytes>>>(w1, w2, it & 1, it == 0 ? 1 : 0);
    }
    // NITER even -> final state in g_bufA (parity arg 1)
    final_kernel<<<(NB*Hh*Ww + 255)/256, 256>>>(out, 1);
}

// round 13
// speedup vs baseline: 1.0797x; 1.0579x over previous
#include <cuda_runtime.h>

#define Hh 128
#define Ww 128
#define NB 32
#define CCH 16
#define NITER 30

#define TW 16
#define TH 16
#define IW 18
#define IH 18
#define NPX 256           // pixels per tile
#define NTILES 2048
#define NCTA 296          // 148 * 2 (512-thread CTAs)
#define NTHR 512

typedef unsigned long long ULL;

__device__ float g_bufA[NB*CCH*Hh*Ww];
__device__ float g_bufB[NB*CCH*Hh*Ww];
__device__ unsigned char g_pre[NB*Hh*Ww];
__device__ unsigned char g_alive[NB*Hh*Ww];

__device__ __forceinline__ ULL pk2(float a, float b){
    ULL r; asm("mov.b64 %0, {%1,%2};" : "=l"(r) : "f"(a), "f"(b)); return r;
}
__device__ __forceinline__ void fma2(ULL &d, ULL a, ULL b){
    asm("fma.rn.f32x2 %0, %1, %2, %0;" : "+l"(d) : "l"(a), "l"(b));
}
__device__ __forceinline__ float lo2(ULL v){ return __uint_as_float((unsigned)v); }
__device__ __forceinline__ float hi2(ULL v){ return __uint_as_float((unsigned)(v>>32)); }

__global__ void init_kernel(const float* __restrict__ inp){
    int p = blockIdx.x*blockDim.x + threadIdx.x;
    const int total = NB*CCH*Hh*Ww;
    if (p >= total) return;
    int hw = p % (Hh*Ww);
    int c  = (p / (Hh*Ww)) % CCH;
    int n  = p / (CCH*Hh*Ww);
    float v;
    if (c == 0)       v = 1.0f - inp[(n*10 + 0)*Hh*Ww + hw];
    else if (c <= 10) v = inp[(n*10 + (c-1))*Hh*Ww + hw];
    else              v = 0.0f;
    g_bufA[p] = v;
    if (c == 0) g_alive[n*Hh*Ww + hw] = 1;
}

// smem float layout (16448 floats = 65792 B):
//   sw1f: [0, 2304)        w1 transposed [k][o]
//   sw2f: [2304, 3072)     w2 transposed [o][j]
//   spf:  [3072, 11264)    sobel rows [32][256]; after GEMM1: H rows 0..31
//   scf:  [11264, 16448)   cell tile 16*18*18; after GEMM1: H rows 32..47
__global__ void __launch_bounds__(NTHR, 2)
step_kernel(const float* __restrict__ w1, const float* __restrict__ w2, int parity)
{
    extern __shared__ float smem_f[];
    float* sw1f = smem_f;
    float* sw2f = smem_f + 2304;
    float* spf  = smem_f + 3072;
    float* scf  = smem_f + 11264;

    const float* __restrict__ src = parity ? g_bufB : g_bufA;
    float* __restrict__ dst       = parity ? g_bufA : g_bufB;

    const int tid = threadIdx.x;

    // ---- stage weights ONCE per CTA (plain floats, transposed) ----
    for (int i = tid; i < 48*48; i += NTHR) {
        int k = i / 48, o = i % 48;
        sw1f[i] = w1[o*48 + k];
    }
    for (int i = tid; i < 48*16; i += NTHR) {
        int o = i >> 4, j = i & 15;
        sw2f[i] = w2[j*48 + o];
    }

    #pragma unroll 1
    for (int tile = blockIdx.x; tile < NTILES; tile += NCTA) {
        const int n   = tile >> 6;
        const int rem = tile & 63;
        const int gy0 = (rem >> 3) * TH;
        const int gx0 = (rem & 7) * TW;

        // ---- stage cell tile (masked, zero-padded halo) ----
        const unsigned char* arow = g_alive + n*Hh*Ww;
        for (int i = tid; i < CCH*IH*IW; i += NTHR) {
            int sx = i % IW;
            int t  = i / IW;
            int sy = t % IH;
            int c  = t / IH;
            int gx = gx0 + sx - 1, gy = gy0 + sy - 1;
            float v = 0.0f;
            if ((unsigned)gx < (unsigned)Ww && (unsigned)gy < (unsigned)Hh) {
                int hw = gy*Ww + gx;
                if (arow[hw])
                    v = src[(size_t)(n*CCH + c)*(Hh*Ww) + hw];
            }
            scf[(c*IH + sy)*IW + sx] = v;
        }
        __syncthreads();

        // ---- perception: sobel -> spf rows (cell stays in scf); 4 thr/pair ----
        {
            const int pair = tid & 127;          // 128 pixel-pairs
            const int q    = tid >> 7;           // 0..3 -> 4 channels each
            const int py = pair >> 3, px2 = pair & 7;
            const int sy = py + 1;
            #pragma unroll
            for (int cc = 0; cc < 4; cc++) {
                int c = 4*q + cc;
                const float2* r0 = (const float2*)(scf + (c*IH + sy - 1)*IW + 2*px2);
                const float2* r1 = (const float2*)((const float*)r0 + IW);
                const float2* r2 = (const float2*)((const float*)r1 + IW);
                float2 v00 = r0[0], v01 = r0[1];
                float2 v10 = r1[0], v11 = r1[1];
                float2 v20 = r2[0], v21 = r2[1];
                float a0=v00.x,a1=v00.y,a2=v01.x,a3=v01.y;
                float m0=v10.x,m1=v10.y,m2=v11.x,m3=v11.y;
                float q0=v20.x,q1=v20.y,q2=v21.x,q3=v21.y;
                float gxl = ((a2 - a0) + 2.f*(m2 - m0) + (q2 - q0)) * 0.125f;
                float gxh = ((a3 - a1) + 2.f*(m3 - m1) + (q3 - q1)) * 0.125f;
                float gyl = ((q0 - a0) + 2.f*(q1 - a1) + (q2 - a2)) * 0.125f;
                float gyh = ((q1 - a1) + 2.f*(q2 - a2) + (q3 - a3)) * 0.125f;
                *(float2*)(spf + c*NPX + 2*pair)        = make_float2(gxl, gxh);
                *(float2*)(spf + (16 + c)*NPX + 2*pair) = make_float2(gyl, gyh);
                if (c == 0) {
                    float t0 = fmaxf(fmaxf(a0,a1),a2);
                    float t1 = fmaxf(fmaxf(m0,m1),m2);
                    float t2 = fmaxf(fmaxf(q0,q1),q2);
                    float pl = fmaxf(fmaxf(t0,t1),t2);
                    float u0 = fmaxf(fmaxf(a1,a2),a3);
                    float u1 = fmaxf(fmaxf(m1,m2),m3);
                    float u2 = fmaxf(fmaxf(q1,q2),q3);
                    float ph = fmaxf(fmaxf(u0,u1),u2);
                    uchar2 pm;
                    pm.x = (pl > 0.1f) ? 1 : 0;
                    pm.y = (ph > 0.1f) ? 1 : 0;
                    *reinterpret_cast<uchar2*>(g_pre + (n*Hh + gy0 + py)*Ww + gx0 + 2*px2) = pm;
                }
            }
        }
        __syncthreads();

        // ---- GEMM1: H = relu(W1*perc); thread = (g in 128 px-lanes, ob of 12 o) ----
        {
            const int g  = tid & 127;    // px = g, g+128
            const int ob = tid >> 7;     // o = 12*ob .. 12*ob+11
            ULL acc[2][6];
            #pragma unroll
            for (int m = 0; m < 2; m++)
                #pragma unroll
                for (int j = 0; j < 6; j++) acc[m][j] = 0ull;

            const int off0 = (((g       ) >> 4) + 1)*IW + ((g       ) & 15) + 1;
            const int off1 = (((g + 128 ) >> 4) + 1)*IW + ((g + 128 ) & 15) + 1;

            // part A: k = 0..15, cell from scf
            #pragma unroll 4
            for (int k = 0; k < 16; k++) {
                float p0 = scf[k*(IH*IW) + off0];
                float p1 = scf[k*(IH*IW) + off1];
                ULL s0 = pk2(p0,p0), s1 = pk2(p1,p1);
                const ulonglong2* wv = (const ulonglong2*)(sw1f + k*48 + 12*ob);
                ulonglong2 w0 = wv[0], w1v = wv[1], w2v = wv[2];
                fma2(acc[0][0], s0, w0.x);  fma2(acc[1][0], s1, w0.x);
                fma2(acc[0][1], s0, w0.y);  fma2(acc[1][1], s1, w0.y);
                fma2(acc[0][2], s0, w1v.x); fma2(acc[1][2], s1, w1v.x);
                fma2(acc[0][3], s0, w1v.y); fma2(acc[1][3], s1, w1v.y);
                fma2(acc[0][4], s0, w2v.x); fma2(acc[1][4], s1, w2v.x);
                fma2(acc[0][5], s0, w2v.y); fma2(acc[1][5], s1, w2v.y);
            }
            // part B: k = 16..47, sobel from spf rows 0..31
            #pragma unroll 4
            for (int k2 = 0; k2 < 32; k2++) {
                const float* pr = spf + k2*NPX + g;
                float p0 = pr[0], p1 = pr[128];
                ULL s0 = pk2(p0,p0), s1 = pk2(p1,p1);
                const ulonglong2* wv = (const ulonglong2*)(sw1f + (16 + k2)*48 + 12*ob);
                ulonglong2 w0 = wv[0], w1v = wv[1], w2v = wv[2];
                fma2(acc[0][0], s0, w0.x);  fma2(acc[1][0], s1, w0.x);
                fma2(acc[0][1], s0, w0.y);  fma2(acc[1][1], s1, w0.y);
                fma2(acc[0][2], s0, w1v.x); fma2(acc[1][2], s1, w1v.x);
                fma2(acc[0][3], s0, w1v.y); fma2(acc[1][3], s1, w1v.y);
                fma2(acc[0][4], s0, w2v.x); fma2(acc[1][4], s1, w2v.x);
                fma2(acc[0][5], s0, w2v.y); fma2(acc[1][5], s1, w2v.y);
            }
            __syncthreads();   // sp/sc reads done before H overwrites
            // store H: rows 0..31 -> spf, rows 32..47 -> scf
            #pragma unroll
            for (int op = 0; op < 6; op++) {
                int o = 12*ob + 2*op;          // even; pair (o,o+1) never straddles 32
                float* r0 = (o < 32) ? (spf + o*NPX) : (scf + (o - 32)*NPX);
                float* r1 = r0 + NPX;
                r0[g]       = fmaxf(lo2(acc[0][op]), 0.f);
                r0[g + 128] = fmaxf(lo2(acc[1][op]), 0.f);
                r1[g]       = fmaxf(hi2(acc[0][op]), 0.f);
                r1[g + 128] = fmaxf(hi2(acc[1][op]), 0.f);
            }
        }
        __syncthreads();

        // ---- GEMM2: cur = W2*H + residual; thread = (g2 in 128, jg of 4 j) ----
        {
            const int g2 = tid & 127;    // px = g2, g2+128
            const int jg = tid >> 7;     // j = 4*jg .. 4*jg+3
            const int pxA = g2, pxB = g2 + 128;
            const int pyA = pxA >> 4, sxA = pxA & 15;
            const int pyB = pxB >> 4, sxB = pxB & 15;
            const int hwA = (gy0 + pyA)*Ww + gx0 + sxA;
            const int hwB = (gy0 + pyB)*Ww + gx0 + sxB;

            // residual: masked cell re-read from global (L2-resident)
            float rA[4], rB[4];
            {
                const unsigned char aA = arow[hwA];
                const unsigned char aB = arow[hwB];
                #pragma unroll
                for (int jj = 0; jj < 4; jj++) {
                    int j = 4*jg + jj;
                    const float* sj = src + (size_t)(n*CCH + j)*(Hh*Ww);
                    rA[jj] = aA ? sj[hwA] : 0.0f;
                    rB[jj] = aB ? sj[hwB] : 0.0f;
                }
            }

            ULL cA[2], cB[2];
            cA[0] = cA[1] = cB[0] = cB[1] = 0ull;

            #pragma unroll 8
            for (int o = 0; o < 32; o++) {
                const float* hs = spf + o*NPX;
                float ha = hs[g2], hb = hs[g2 + 128];
                ULL sa = pk2(ha,ha), sb = pk2(hb,hb);
                const ulonglong2* wv = (const ulonglong2*)(sw2f + o*16 + 4*jg);
                ulonglong2 w0 = wv[0];
                fma2(cA[0], sa, w0.x); fma2(cA[1], sa, w0.y);
                fma2(cB[0], sb, w0.x); fma2(cB[1], sb, w0.y);
            }
            #pragma unroll 8
            for (int o = 32; o < 48; o++) {
                const float* hs = scf + (o - 32)*NPX;
                float ha = hs[g2], hb = hs[g2 + 128];
                ULL sa = pk2(ha,ha), sb = pk2(hb,hb);
                const ulonglong2* wv = (const ulonglong2*)(sw2f + o*16 + 4*jg);
                ulonglong2 w0 = wv[0];
                fma2(cA[0], sa, w0.x); fma2(cA[1], sa, w0.y);
                fma2(cB[0], sb, w0.x); fma2(cB[1], sb, w0.y);
            }

            // store with residual
            #pragma unroll
            for (int q = 0; q < 2; q++) {
                int j = 4*jg + 2*q;
                float* d0 = dst + (size_t)(n*CCH + j)*(Hh*Ww);
                float* d1 = d0 + Hh*Ww;
                d0[hwA] = lo2(cA[q]) + rA[2*q];
                d1[hwA] = hi2(cA[q]) + rA[2*q + 1];
                d0[hwB] = lo2(cB[q]) + rB[2*q];
                d1[hwB] = hi2(cB[q]) + rB[2*q + 1];
            }
        }
        __syncthreads();   // H reads done before next tile's staging
    }
}

// post mask (3x3 maxpool of new cur ch0) & alive byte; last iter writes output.
__global__ void alive_kernel(float* __restrict__ outfinal, int parity, int writeOut)
{
    const float* __restrict__ cur = parity ? g_bufA : g_bufB;
    int p = blockIdx.x*blockDim.x + threadIdx.x;
    if (p >= NB*Hh*Ww) return;
    int x = p % Ww;
    int y = (p / Ww) % Hh;
    int n = p / (Hh*Ww);
    const float* c0 = cur + (size_t)n*CCH*Hh*Ww;
    float m = -1e30f;
    #pragma unroll
    for (int dy = -1; dy <= 1; dy++) {
        int yy = y + dy;
        if (yy < 0 || yy >= Hh) continue;
        const float* row = c0 + yy*Ww;
        #pragma unroll
        for (int dx = -1; dx <= 1; dx++) {
            int xx = x + dx;
            if (xx < 0 || xx >= Ww) continue;
            m = fmaxf(m, row[xx]);
        }
    }
    bool alive = (m > 0.1f) && (g_pre[p] != 0);
    g_alive[p] = alive ? 1 : 0;
    if (writeOut) {
        size_t base = ((size_t)n*CCH)*Hh*Ww + (size_t)y*Ww + x;
        #pragma unroll
        for (int c = 1; c <= 10; c++) {
            float v = alive ? cur[base + (size_t)c*Hh*Ww] : 0.0f;
            outfinal[(((size_t)n*10 + (c-1))*Hh + y)*Ww + x] = v;
        }
    }
}

extern "C" void kernel_launch(void* const* d_in, const int* in_sizes, int n_in,
                              void* d_out, int out_size)
{
    const float *inp = nullptr, *w1 = nullptr, *w2 = nullptr;
    for (int i = 0; i < n_in; i++) {
        if (in_sizes[i] == 48*48)      w1 = (const float*)d_in[i];
        else if (in_sizes[i] == 16*48) w2 = (const float*)d_in[i];
        else                           inp = (const float*)d_in[i];
    }
    float* out = (float*)d_out;

    const int smemBytes = 16448*4;   // 65792 B
    cudaFuncSetAttribute(step_kernel, cudaFuncAttributeMaxDynamicSharedMemorySize, smemBytes);

    init_kernel<<<(NB*CCH*Hh*Ww + 255)/256, 256>>>(inp);

    const int g2 = (NB*Hh*Ww + 255)/256;
    for (int it = 0; it < NITER; it++) {
        int parity = it & 1;
        step_kernel<<<NCTA, NTHR, smemBytes>>>(w1, w2, parity);
        alive_kernel<<<g2, 256>>>(out, parity, (it == NITER-1) ? 1 : 0);
    }
}